// round 7
// baseline (speedup 1.0000x reference)
#include <cuda_runtime.h>
#include <math.h>

#define N_NODES 50000
#define F_IN 128
#define H 64
#define HEADS 4
#define E_MAX 800000
#define NH (N_NODES * H)
#define NB ((N_NODES + 255) / 256)   // 196 scan blocks

// ---------------- scratch ----------------
__device__ float g_xw[NH];
__device__ int   g_degi[N_NODES];
__device__ float g_dinv[N_NODES];
__device__ int   g_off[N_NODES];
__device__ int   g_cursor[N_NODES];
__device__ int   g_bsum[256];
__device__ int   g_bcarry[256];
__device__ int   g_csr[E_MAX];              // src node per CSR slot
__device__ float g_alpha[E_MAX * HEADS];    // logits, then exp (CSR order)
__device__ float g_h1[NH];
__device__ float g_hg[N_NODES * HEADS * H];
__device__ float g_asrc[N_NODES * HEADS];
__device__ float g_adst[N_NODES * HEADS];
__device__ float g_eself[N_NODES * HEADS];
__device__ float g_exself[N_NODES * HEADS]; // self exp (unscaled)
__device__ float g_esum[N_NODES * HEADS];   // rs = 0.25/sum
__device__ float g_h2[NH];                  // GAT accum (raw; bias/relu at readers)
__device__ float g_sagg[NH];

__device__ __forceinline__ float leaky(float v) { return v > 0.f ? v : 0.2f * v; }

// ---------------- degree count ----------------
__global__ void k_zero_deg() {
    int i = blockIdx.x * blockDim.x + threadIdx.x;
    if (i < N_NODES) g_degi[i] = 0;
}

__global__ void k_degcnt(const int* __restrict__ ei, int E) {
    int e = blockIdx.x * blockDim.x + threadIdx.x;
    if (e >= E) return;
    atomicAdd(&g_degi[ei[E + e]], 1);
}

// ---------------- prefix scan (3 kernels) ----------------
__global__ void k_scan1() {
    int t = threadIdx.x;
    int i = blockIdx.x * 256 + t;
    int val = (i < N_NODES) ? g_degi[i] : 0;
    int lane = t & 31, w = t >> 5;
    int x = val;
#pragma unroll
    for (int o = 1; o < 32; o <<= 1) {
        int y = __shfl_up_sync(0xffffffffu, x, o);
        if (lane >= o) x += y;
    }
    __shared__ int wsum[8];
    if (lane == 31) wsum[w] = x;
    __syncthreads();
    if (w == 0) {
        int s = (lane < 8) ? wsum[lane] : 0;
#pragma unroll
        for (int o = 1; o < 8; o <<= 1) {
            int y = __shfl_up_sync(0xffffffffu, s, o);
            if (lane >= o) s += y;
        }
        if (lane < 8) wsum[lane] = s;
    }
    __syncthreads();
    int incl = x + (w > 0 ? wsum[w - 1] : 0);
    if (i < N_NODES) g_off[i] = incl - val;
    if (t == 255) g_bsum[blockIdx.x] = incl;
}

__global__ void k_scan2() {
    int t = threadIdx.x;
    int val = (t < NB) ? g_bsum[t] : 0;
    int lane = t & 31, w = t >> 5;
    int x = val;
#pragma unroll
    for (int o = 1; o < 32; o <<= 1) {
        int y = __shfl_up_sync(0xffffffffu, x, o);
        if (lane >= o) x += y;
    }
    __shared__ int wsum[8];
    if (lane == 31) wsum[w] = x;
    __syncthreads();
    if (w == 0) {
        int s = (lane < 8) ? wsum[lane] : 0;
#pragma unroll
        for (int o = 1; o < 8; o <<= 1) {
            int y = __shfl_up_sync(0xffffffffu, s, o);
            if (lane >= o) s += y;
        }
        if (lane < 8) wsum[lane] = s;
    }
    __syncthreads();
    int incl = x + (w > 0 ? wsum[w - 1] : 0);
    if (t < NB) g_bcarry[t] = incl - val;
}

__global__ void k_scan3() {
    int i = blockIdx.x * blockDim.x + threadIdx.x;
    if (i >= N_NODES) return;
    int off = g_off[i] + g_bcarry[i >> 8];
    g_off[i] = off;
    g_cursor[i] = off;
    g_dinv[i] = rsqrtf((float)g_degi[i] + 1.f);
}

__global__ void k_fill(const int* __restrict__ ei, int E) {
    int e = blockIdx.x * blockDim.x + threadIdx.x;
    if (e >= E) return;
    int r = ei[e], cl = ei[E + e];
    int pos = atomicAdd(&g_cursor[cl], 1);
    g_csr[pos] = r;
}

// ---------------- dense: xw = x @ W1 (128->64), 128 nodes/block, 8x8 tiles ----------------
#define XW_SMEM ((2048 + 2112) * 16)
__global__ __launch_bounds__(128) void k_xw(const float* __restrict__ x,
                                            const float* __restrict__ W1) {
    extern __shared__ float4 sm4[];
    float4* Ws4 = sm4;           // 128 k x 16 f4
    float4* xs4 = sm4 + 2048;    // 64 k x 33 f4
    float* xs = (float*)xs4;
    int t = threadIdx.x;
    int n0 = blockIdx.x * 128;

#pragma unroll
    for (int i = 0; i < 16; i++) Ws4[t + 128 * i] = ((const float4*)W1)[t + 128 * i];

    int nq = t >> 3, cq = t & 7;
    float acc[8][8] = {};
    for (int ch = 0; ch < 2; ch++) {
        __syncthreads();
        int n = n0 + t;
        if (n < N_NODES) {
            const float4* xr = (const float4*)&x[(size_t)n * F_IN + ch * 64];
#pragma unroll
            for (int j = 0; j < 16; j++) {
                float4 v = xr[j];
                xs[(j * 4 + 0) * 132 + t] = v.x;
                xs[(j * 4 + 1) * 132 + t] = v.y;
                xs[(j * 4 + 2) * 132 + t] = v.z;
                xs[(j * 4 + 3) * 132 + t] = v.w;
            }
        } else {
#pragma unroll
            for (int j = 0; j < 64; j++) xs[j * 132 + t] = 0.f;
        }
        __syncthreads();
#pragma unroll 2
        for (int k = 0; k < 64; k++) {
            float4 a0 = xs4[k * 33 + nq * 2];
            float4 a1 = xs4[k * 33 + nq * 2 + 1];
            int kg = ch * 64 + k;
            float4 w0 = Ws4[kg * 16 + cq * 2];
            float4 w1 = Ws4[kg * 16 + cq * 2 + 1];
            float av[8] = {a0.x, a0.y, a0.z, a0.w, a1.x, a1.y, a1.z, a1.w};
            float wv[8] = {w0.x, w0.y, w0.z, w0.w, w1.x, w1.y, w1.z, w1.w};
#pragma unroll
            for (int i = 0; i < 8; i++)
#pragma unroll
                for (int j = 0; j < 8; j++) acc[i][j] += av[i] * wv[j];
        }
    }
#pragma unroll
    for (int i = 0; i < 8; i++) {
        int n = n0 + nq * 8 + i;
        if (n < N_NODES) {
            *(float4*)&g_xw[n * 64 + cq * 8] =
                make_float4(acc[i][0], acc[i][1], acc[i][2], acc[i][3]);
            *(float4*)&g_xw[n * 64 + cq * 8 + 4] =
                make_float4(acc[i][4], acc[i][5], acc[i][6], acc[i][7]);
        }
    }
}

// ---------------- GCN gather: h1[n] = dinv[n] * sum_e dinv[r]*xw[r] ----------------
__global__ __launch_bounds__(256) void k_gcn_gather() {
    int t = threadIdx.x;
    int n = blockIdx.x * 4 + (t >> 6);
    if (n >= N_NODES) return;
    int c = t & 63;
    int off = g_off[n], dg = g_degi[n];
    float acc = 0.f;
    int rN = (dg > 0) ? g_csr[off] : 0;
    for (int k = 0; k < dg; k++) {
        int r = rN;
        if (k + 1 < dg) rN = g_csr[off + k + 1];
        acc += g_dinv[r] * g_xw[r * 64 + c];
    }
    g_h1[n * 64 + c] = acc * g_dinv[n];
}

// ---------------- dense: hg = relu(gcn) @ Wg + attention dots; 64 nodes/block ----------------
#define HG_SMEM ((4096 + 1088) * 16)
__global__ __launch_bounds__(256) void k_hg(const float* __restrict__ Wg,
                                            const float* __restrict__ b1,
                                            const float* __restrict__ att_src,
                                            const float* __restrict__ att_dst) {
    extern __shared__ float4 sm4[];
    float4* Ws4 = sm4;           // 64 k x 64 f4
    float4* hs4 = sm4 + 4096;    // 64 k x 17 f4
    float* hs = (float*)hs4;
    int t = threadIdx.x;
    int n0 = blockIdx.x * 64;

#pragma unroll
    for (int i = 0; i < 16; i++) Ws4[t + 256 * i] = ((const float4*)Wg)[t + 256 * i];

    {
        int nl = t & 63, kq = t >> 6;
        int n = n0 + nl;
        if (n < N_NODES) {
            float d = g_dinv[n]; float d2 = d * d;
#pragma unroll
            for (int j = 0; j < 4; j++) {
                int k0 = kq * 16 + j * 4;
                float4 hv = *(const float4*)&g_h1[n * 64 + k0];
                float4 xv = *(const float4*)&g_xw[n * 64 + k0];
                float4 bv = *(const float4*)&b1[k0];
                hs[(k0 + 0) * 68 + nl] = fmaxf(hv.x + d2 * xv.x + bv.x, 0.f);
                hs[(k0 + 1) * 68 + nl] = fmaxf(hv.y + d2 * xv.y + bv.y, 0.f);
                hs[(k0 + 2) * 68 + nl] = fmaxf(hv.z + d2 * xv.z + bv.z, 0.f);
                hs[(k0 + 3) * 68 + nl] = fmaxf(hv.w + d2 * xv.w + bv.w, 0.f);
            }
        } else {
#pragma unroll
            for (int j = 0; j < 16; j++) hs[(kq * 16 + j) * 68 + nl] = 0.f;
        }
    }
    __syncthreads();

    int nq = t >> 5, cq = t & 31;
    int lane = t & 31;
    float acc[8][8] = {};
#pragma unroll 2
    for (int k = 0; k < 64; k++) {
        float4 a0 = hs4[k * 17 + nq * 2];
        float4 a1 = hs4[k * 17 + nq * 2 + 1];
        float4 w0 = Ws4[k * 64 + cq * 2];
        float4 w1 = Ws4[k * 64 + cq * 2 + 1];
        float av[8] = {a0.x, a0.y, a0.z, a0.w, a1.x, a1.y, a1.z, a1.w};
        float wv[8] = {w0.x, w0.y, w0.z, w0.w, w1.x, w1.y, w1.z, w1.w};
#pragma unroll
        for (int i = 0; i < 8; i++)
#pragma unroll
            for (int j = 0; j < 8; j++) acc[i][j] += av[i] * wv[j];
    }
    int c0 = cq * 8;
    float4 s0 = *(const float4*)&att_src[c0];
    float4 s1 = *(const float4*)&att_src[c0 + 4];
    float4 d0 = *(const float4*)&att_dst[c0];
    float4 d1 = *(const float4*)&att_dst[c0 + 4];
    int head = cq >> 3;
#pragma unroll
    for (int i = 0; i < 8; i++) {
        int n = n0 + nq * 8 + i;
        bool valid = (n < N_NODES);
        if (valid) {
            *(float4*)&g_hg[(size_t)n * 256 + c0] =
                make_float4(acc[i][0], acc[i][1], acc[i][2], acc[i][3]);
            *(float4*)&g_hg[(size_t)n * 256 + c0 + 4] =
                make_float4(acc[i][4], acc[i][5], acc[i][6], acc[i][7]);
        }
        float sp = acc[i][0] * s0.x + acc[i][1] * s0.y + acc[i][2] * s0.z + acc[i][3] * s0.w
                 + acc[i][4] * s1.x + acc[i][5] * s1.y + acc[i][6] * s1.z + acc[i][7] * s1.w;
        float dp = acc[i][0] * d0.x + acc[i][1] * d0.y + acc[i][2] * d0.z + acc[i][3] * d0.w
                 + acc[i][4] * d1.x + acc[i][5] * d1.y + acc[i][6] * d1.z + acc[i][7] * d1.w;
        sp += __shfl_down_sync(0xffffffffu, sp, 4, 8);
        sp += __shfl_down_sync(0xffffffffu, sp, 2, 8);
        sp += __shfl_down_sync(0xffffffffu, sp, 1, 8);
        dp += __shfl_down_sync(0xffffffffu, dp, 4, 8);
        dp += __shfl_down_sync(0xffffffffu, dp, 2, 8);
        dp += __shfl_down_sync(0xffffffffu, dp, 1, 8);
        if ((lane & 7) == 0 && valid) {
            int o = n * 4 + head;
            g_asrc[o] = sp;
            g_adst[o] = dp;
            g_eself[o] = leaky(sp + dp);
        }
    }
}

// ---------------- GAT softmax: one warp per node, 2 passes over CSR ----------------
__global__ __launch_bounds__(256) void k_gat_softmax() {
    int t = threadIdx.x;
    int lane = t & 31;
    int n = blockIdx.x * 8 + (t >> 5);
    if (n >= N_NODES) return;
    int off = g_off[n], dg = g_degi[n];
    float4 dstv = *(const float4*)&g_adst[n * 4];
    float4 es = *(const float4*)&g_eself[n * 4];
    float4 m = es;
    // pass 1: logits -> g_alpha, running max
    for (int p = off + lane; p < off + dg; p += 32) {
        int r = g_csr[p];
        float4 s = *(const float4*)&g_asrc[r * 4];
        float4 l;
        l.x = leaky(s.x + dstv.x); l.y = leaky(s.y + dstv.y);
        l.z = leaky(s.z + dstv.z); l.w = leaky(s.w + dstv.w);
        *(float4*)&g_alpha[(size_t)p * 4] = l;
        m.x = fmaxf(m.x, l.x); m.y = fmaxf(m.y, l.y);
        m.z = fmaxf(m.z, l.z); m.w = fmaxf(m.w, l.w);
    }
#pragma unroll
    for (int o = 16; o > 0; o >>= 1) {
        m.x = fmaxf(m.x, __shfl_xor_sync(0xffffffffu, m.x, o));
        m.y = fmaxf(m.y, __shfl_xor_sync(0xffffffffu, m.y, o));
        m.z = fmaxf(m.z, __shfl_xor_sync(0xffffffffu, m.z, o));
        m.w = fmaxf(m.w, __shfl_xor_sync(0xffffffffu, m.w, o));
    }
    // pass 2: exp in place, running sum
    float4 sum = make_float4(0.f, 0.f, 0.f, 0.f);
    for (int p = off + lane; p < off + dg; p += 32) {
        float4 l = *(const float4*)&g_alpha[(size_t)p * 4];
        float4 ex;
        ex.x = __expf(l.x - m.x); ex.y = __expf(l.y - m.y);
        ex.z = __expf(l.z - m.z); ex.w = __expf(l.w - m.w);
        *(float4*)&g_alpha[(size_t)p * 4] = ex;
        sum.x += ex.x; sum.y += ex.y; sum.z += ex.z; sum.w += ex.w;
    }
#pragma unroll
    for (int o = 16; o > 0; o >>= 1) {
        sum.x += __shfl_xor_sync(0xffffffffu, sum.x, o);
        sum.y += __shfl_xor_sync(0xffffffffu, sum.y, o);
        sum.z += __shfl_xor_sync(0xffffffffu, sum.z, o);
        sum.w += __shfl_xor_sync(0xffffffffu, sum.w, o);
    }
    float4 sf;
    sf.x = __expf(es.x - m.x); sf.y = __expf(es.y - m.y);
    sf.z = __expf(es.z - m.z); sf.w = __expf(es.w - m.w);
    sum.x += sf.x; sum.y += sf.y; sum.z += sf.z; sum.w += sf.w;
    if (lane == 0) {
        float4 rs;
        rs.x = 0.25f * __frcp_rn(sum.x); rs.y = 0.25f * __frcp_rn(sum.y);
        rs.z = 0.25f * __frcp_rn(sum.z); rs.w = 0.25f * __frcp_rn(sum.w);
        *(float4*)&g_esum[n * 4] = rs;
        *(float4*)&g_exself[n * 4] = sf;
    }
}

// ---------------- GAT gather: h2[n] = sum_h rs_h * (sf_h*hg[n,h] + sum_e ex_eh*hg[r,h]) ----------------
__global__ __launch_bounds__(256) void k_gat_gather() {
    int t = threadIdx.x;
    int n = blockIdx.x * 4 + (t >> 6);
    if (n >= N_NODES) return;
    int c = t & 63;
    int off = g_off[n], dg = g_degi[n];
    float4 rs = *(const float4*)&g_esum[n * 4];
    float4 sf = *(const float4*)&g_exself[n * 4];
    const float* hgn = &g_hg[(size_t)n * 256 + c];
    float a0 = sf.x * hgn[0], a1 = sf.y * hgn[64], a2 = sf.z * hgn[128], a3 = sf.w * hgn[192];
    int rN = (dg > 0) ? g_csr[off] : 0;
    for (int k = 0; k < dg; k++) {
        int r = rN;
        if (k + 1 < dg) rN = g_csr[off + k + 1];
        float4 ex = *(const float4*)&g_alpha[(size_t)(off + k) * 4];
        const float* hgr = &g_hg[(size_t)r * 256 + c];
        a0 += ex.x * hgr[0];
        a1 += ex.y * hgr[64];
        a2 += ex.z * hgr[128];
        a3 += ex.w * hgr[192];
    }
    g_h2[n * 64 + c] = rs.x * a0 + rs.y * a1 + rs.z * a2 + rs.w * a3;
}

// ---------------- SAGE gather: sagg[n] = sum_e relu(h2[r]+bg) ----------------
__global__ __launch_bounds__(256) void k_sage_gather(const float* __restrict__ bg) {
    int t = threadIdx.x;
    int n = blockIdx.x * 4 + (t >> 6);
    if (n >= N_NODES) return;
    int c = t & 63;
    int off = g_off[n], dg = g_degi[n];
    float bc = bg[c];
    float acc = 0.f;
    int rN = (dg > 0) ? g_csr[off] : 0;
    for (int k = 0; k < dg; k++) {
        int r = rN;
        if (k + 1 < dg) rN = g_csr[off + k + 1];
        acc += fmaxf(g_h2[r * 64 + c] + bc, 0.f);
    }
    g_sagg[n * 64 + c] = acc;
}

// ---------------- final: stacked GEMM [m;h]@[Wl;Wr] + bl, then heads ----------------
#define FIN_SMEM (5184 * 16 + 512)
__global__ __launch_bounds__(128) void k_final(
    const float* __restrict__ bl, const float* __restrict__ Wl,
    const float* __restrict__ Wr, const float* __restrict__ bg,
    const float* __restrict__ a1_w, const float* __restrict__ a1_b,
    const float* __restrict__ a2_w, const float* __restrict__ a2_b,
    const float* __restrict__ r1_w, const float* __restrict__ r1_b,
    const float* __restrict__ r2_w, const float* __restrict__ r2_b,
    float* __restrict__ out) {
    extern __shared__ float4 sm4[];
    float4* Ws4  = sm4;
    float4* xs4  = sm4 + 2048;
    float4* hw14 = sm4 + 4160;
    float* tail = (float*)(sm4 + 5184);
    float* hw2 = tail;
    float* hb1 = tail + 64;
    float* xs  = (float*)xs4;
    float* hw1 = (float*)hw14;
    int t = threadIdx.x;
    int n0 = blockIdx.x * 128;

#pragma unroll
    for (int i = 0; i < 8; i++) {
        Ws4[t + 128 * i]        = ((const float4*)Wl)[t + 128 * i];
        Ws4[1024 + t + 128 * i] = ((const float4*)Wr)[t + 128 * i];
    }
#pragma unroll
    for (int i = 0; i < 4; i++) {
        hw14[t + 128 * i]       = ((const float4*)a1_w)[t + 128 * i];
        hw14[512 + t + 128 * i] = ((const float4*)r1_w)[t + 128 * i];
    }
    if (t < 32) {
        hw2[t] = a2_w[t]; hw2[32 + t] = r2_w[t];
        hb1[t] = a1_b[t]; hb1[32 + t] = r1_b[t];
    }

    int nq = t >> 3, cq = t & 7;
    float4 bl0 = *(const float4*)&bl[cq * 8];
    float4 bl1 = *(const float4*)&bl[cq * 8 + 4];
    float blv[8] = {bl0.x, bl0.y, bl0.z, bl0.w, bl1.x, bl1.y, bl1.z, bl1.w};
    float acc[8][8];
#pragma unroll
    for (int i = 0; i < 8; i++)
#pragma unroll
        for (int j = 0; j < 8; j++) acc[i][j] = blv[j];

    for (int ch = 0; ch < 2; ch++) {
        __syncthreads();
        int n = n0 + t;
        if (n < N_NODES) {
            if (ch == 0) {
                float inv = __frcp_rn(fmaxf((float)g_degi[n], 1.f));
#pragma unroll
                for (int j = 0; j < 16; j++) {
                    float4 v = *(const float4*)&g_sagg[n * 64 + j * 4];
                    xs[(j * 4 + 0) * 132 + t] = v.x * inv;
                    xs[(j * 4 + 1) * 132 + t] = v.y * inv;
                    xs[(j * 4 + 2) * 132 + t] = v.z * inv;
                    xs[(j * 4 + 3) * 132 + t] = v.w * inv;
                }
            } else {
#pragma unroll
                for (int j = 0; j < 16; j++) {
                    float4 v = *(const float4*)&g_h2[n * 64 + j * 4];
                    float4 b = *(const float4*)&bg[j * 4];
                    xs[(j * 4 + 0) * 132 + t] = fmaxf(v.x + b.x, 0.f);
                    xs[(j * 4 + 1) * 132 + t] = fmaxf(v.y + b.y, 0.f);
                    xs[(j * 4 + 2) * 132 + t] = fmaxf(v.z + b.z, 0.f);
                    xs[(j * 4 + 3) * 132 + t] = fmaxf(v.w + b.w, 0.f);
                }
            }
        } else {
#pragma unroll
            for (int j = 0; j < 64; j++) xs[j * 132 + t] = 0.f;
        }
        __syncthreads();
#pragma unroll 2
        for (int k = 0; k < 64; k++) {
            float4 a0 = xs4[k * 33 + nq * 2];
            float4 a1 = xs4[k * 33 + nq * 2 + 1];
            int kg = ch * 64 + k;
            float4 w0 = Ws4[kg * 16 + cq * 2];
            float4 w1 = Ws4[kg * 16 + cq * 2 + 1];
            float av[8] = {a0.x, a0.y, a0.z, a0.w, a1.x, a1.y, a1.z, a1.w};
            float wv[8] = {w0.x, w0.y, w0.z, w0.w, w1.x, w1.y, w1.z, w1.w};
#pragma unroll
            for (int i = 0; i < 8; i++)
#pragma unroll
                for (int j = 0; j < 8; j++) acc[i][j] += av[i] * wv[j];
        }
    }
#pragma unroll
    for (int i = 0; i < 8; i++) {
        int n = n0 + nq * 8 + i;
        if (n < N_NODES) {
            *(float4*)&out[(size_t)n * 64 + cq * 8] =
                make_float4(acc[i][0], acc[i][1], acc[i][2], acc[i][3]);
            *(float4*)&out[(size_t)n * 64 + cq * 8 + 4] =
                make_float4(acc[i][4], acc[i][5], acc[i][6], acc[i][7]);
        }
    }
    __syncthreads();

    int w = t >> 5, lane = t & 31;
    int hd = w >> 1, half = w & 1;
    float w1r[64];
#pragma unroll
    for (int c = 0; c < 64; c++) w1r[c] = hw1[hd * 2048 + c * 32 + lane];
    float w2v = hw2[hd * 32 + lane];
    float b1v = hb1[hd * 32 + lane];
    float b2 = hd ? r2_b[0] : a2_b[0];
    for (int ln = half * 64; ln < half * 64 + 64; ln++) {
        int n = n0 + ln;
        if (n >= N_NODES) break;
        float2 ep = *(const float2*)&out[(size_t)n * 64 + lane * 2];
        float z = b1v;
#pragma unroll
        for (int c = 0; c < 64; c++) {
            float ec = __shfl_sync(0xffffffffu, (c & 1) ? ep.y : ep.x, c >> 1);
            z += ec * w1r[c];
        }
        z = fmaxf(z, 0.f) * w2v;
#pragma unroll
        for (int off = 16; off > 0; off >>= 1)
            z += __shfl_down_sync(0xffffffffu, z, off);
        if (lane == 0)
            out[NH + hd * N_NODES + n] = 1.f / (1.f + expf(-z));
    }
}

// ---------------- launch ----------------
extern "C" void kernel_launch(void* const* d_in, const int* in_sizes, int n_in,
                              void* d_out, int out_size) {
    const float* x       = (const float*)d_in[0];
    const int*   ei      = (const int*)d_in[1];
    const float* W1      = (const float*)d_in[2];
    const float* b1      = (const float*)d_in[3];
    const float* Wg      = (const float*)d_in[4];
    const float* att_src = (const float*)d_in[5];
    const float* att_dst = (const float*)d_in[6];
    const float* bg      = (const float*)d_in[7];
    const float* Wl      = (const float*)d_in[8];
    const float* bl      = (const float*)d_in[9];
    const float* Wr      = (const float*)d_in[10];
    const float* a1_w    = (const float*)d_in[11];
    const float* a1_b    = (const float*)d_in[12];
    const float* a2_w    = (const float*)d_in[13];
    const float* a2_b    = (const float*)d_in[14];
    const float* r1_w    = (const float*)d_in[15];
    const float* r1_b    = (const float*)d_in[16];
    const float* r2_w    = (const float*)d_in[17];
    const float* r2_b    = (const float*)d_in[18];
    float* out = (float*)d_out;

    int E = in_sizes[1] / 2;
    const int T = 256;
    int gE = (E + T - 1) / T;
    int gN = (N_NODES + T - 1) / T;
    int gN4 = (N_NODES + 3) / 4;
    int gN8 = (N_NODES + 7) / 8;

    cudaFuncSetAttribute(k_xw,    cudaFuncAttributeMaxDynamicSharedMemorySize, XW_SMEM);
    cudaFuncSetAttribute(k_hg,    cudaFuncAttributeMaxDynamicSharedMemorySize, HG_SMEM);
    cudaFuncSetAttribute(k_final, cudaFuncAttributeMaxDynamicSharedMemorySize, FIN_SMEM);

    k_zero_deg<<<gN, T>>>();
    k_degcnt<<<gE, T>>>(ei, E);
    k_scan1<<<NB, 256>>>();
    k_scan2<<<1, 256>>>();
    k_scan3<<<gN, T>>>();
    k_fill<<<gE, T>>>(ei, E);
    k_xw<<<(N_NODES + 127) / 128, 128, XW_SMEM>>>(x, W1);
    k_gcn_gather<<<gN4, 256>>>();
    k_hg<<<(N_NODES + 63) / 64, 256, HG_SMEM>>>(Wg, b1, att_src, att_dst);
    k_gat_softmax<<<gN8, 256>>>();
    k_gat_gather<<<gN4, 256>>>();
    k_sage_gather<<<gN4, 256>>>(bg);
    k_final<<<(N_NODES + 127) / 128, 128, FIN_SMEM>>>(bl, Wl, Wr, bg,
                                                      a1_w, a1_b, a2_w, a2_b,
                                                      r1_w, r1_b, r2_w, r2_b, out);
}

// round 10
// speedup vs baseline: 1.0253x; 1.0253x over previous
#include <cuda_runtime.h>
#include <cuda_fp16.h>
#include <math.h>
#include <stdint.h>

#define N_NODES 50000
#define F_IN 128
#define H 64
#define HEADS 4
#define E_MAX 800000
#define NH (N_NODES * H)
#define NB ((N_NODES + 255) / 256)

// ---------------- scratch ----------------
__device__ float  g_xw[NH];
__device__ int    g_degi[N_NODES];
__device__ float  g_dinv[N_NODES];
__device__ int    g_off[N_NODES];
__device__ int    g_cursor[N_NODES];
__device__ int    g_bsum[256];
__device__ int    g_bcarry[256];
__device__ int    g_csr[E_MAX];
__device__ float  g_alpha[E_MAX * HEADS];     // unnormalized exp (CSR order)
__device__ float  g_h1[NH];
__device__ __half g_hg[N_NODES * HEADS * H];  // GAT feats, fp16 [n][h][c]
__device__ float  g_asrc[N_NODES * HEADS];
__device__ float  g_adst[N_NODES * HEADS];
__device__ float  g_eself[N_NODES * HEADS];
__device__ float  g_exself[N_NODES * HEADS];  // exp(self-20)
__device__ float  g_esum[N_NODES * HEADS];    // rs = 0.25/sum
__device__ __half g_h2[NH];                   // GAT out (raw; bias/relu at readers), fp16
__device__ float  g_sagg[NH];

__device__ __forceinline__ float leaky(float v) { return v > 0.f ? v : 0.2f * v; }

__device__ __forceinline__ uint32_t h2_bits(__half2 h) {
    return *reinterpret_cast<uint32_t*>(&h);
}
__device__ __forceinline__ __half2 bits_h2(uint32_t u) {
    return *reinterpret_cast<__half2*>(&u);
}

// ---------------- degree count ----------------
__global__ void k_zero_deg() {
    int i = blockIdx.x * blockDim.x + threadIdx.x;
    if (i < N_NODES) g_degi[i] = 0;
}

__global__ void k_degcnt(const int* __restrict__ ei, int E) {
    int e = blockIdx.x * blockDim.x + threadIdx.x;
    if (e >= E) return;
    atomicAdd(&g_degi[ei[E + e]], 1);
}

// ---------------- prefix scan ----------------
__global__ void k_scan1() {
    int t = threadIdx.x;
    int i = blockIdx.x * 256 + t;
    int val = (i < N_NODES) ? g_degi[i] : 0;
    int lane = t & 31, w = t >> 5;
    int x = val;
#pragma unroll
    for (int o = 1; o < 32; o <<= 1) {
        int y = __shfl_up_sync(0xffffffffu, x, o);
        if (lane >= o) x += y;
    }
    __shared__ int wsum[8];
    if (lane == 31) wsum[w] = x;
    __syncthreads();
    if (w == 0) {
        int s = (lane < 8) ? wsum[lane] : 0;
#pragma unroll
        for (int o = 1; o < 8; o <<= 1) {
            int y = __shfl_up_sync(0xffffffffu, s, o);
            if (lane >= o) s += y;
        }
        if (lane < 8) wsum[lane] = s;
    }
    __syncthreads();
    int incl = x + (w > 0 ? wsum[w - 1] : 0);
    if (i < N_NODES) g_off[i] = incl - val;
    if (t == 255) g_bsum[blockIdx.x] = incl;
}

__global__ void k_scan2() {
    int t = threadIdx.x;
    int val = (t < NB) ? g_bsum[t] : 0;
    int lane = t & 31, w = t >> 5;
    int x = val;
#pragma unroll
    for (int o = 1; o < 32; o <<= 1) {
        int y = __shfl_up_sync(0xffffffffu, x, o);
        if (lane >= o) x += y;
    }
    __shared__ int wsum[8];
    if (lane == 31) wsum[w] = x;
    __syncthreads();
    if (w == 0) {
        int s = (lane < 8) ? wsum[lane] : 0;
#pragma unroll
        for (int o = 1; o < 8; o <<= 1) {
            int y = __shfl_up_sync(0xffffffffu, s, o);
            if (lane >= o) s += y;
        }
        if (lane < 8) wsum[lane] = s;
    }
    __syncthreads();
    int incl = x + (w > 0 ? wsum[w - 1] : 0);
    if (t < NB) g_bcarry[t] = incl - val;
}

__global__ void k_scan3() {
    int i = blockIdx.x * blockDim.x + threadIdx.x;
    if (i >= N_NODES) return;
    int off = g_off[i] + g_bcarry[i >> 8];
    g_off[i] = off;
    g_cursor[i] = off;
    g_dinv[i] = rsqrtf((float)g_degi[i] + 1.f);
}

__global__ void k_fill(const int* __restrict__ ei, int E) {
    int e = blockIdx.x * blockDim.x + threadIdx.x;
    if (e >= E) return;
    int r = ei[e], cl = ei[E + e];
    int pos = atomicAdd(&g_cursor[cl], 1);
    g_csr[pos] = r;
}

// ---------------- dense: xw = x @ W1 (128->64), 128 nodes/block, 8x8 tiles ----------------
#define XW_SMEM ((2048 + 2112) * 16)
__global__ __launch_bounds__(128) void k_xw(const float* __restrict__ x,
                                            const float* __restrict__ W1) {
    extern __shared__ float4 sm4[];
    float4* Ws4 = sm4;           // 128 k x 16 f4
    float4* xs4 = sm4 + 2048;    // 64 k x 33 f4
    float* xs = (float*)xs4;
    int t = threadIdx.x;
    int n0 = blockIdx.x * 128;

#pragma unroll
    for (int i = 0; i < 16; i++) Ws4[t + 128 * i] = ((const float4*)W1)[t + 128 * i];

    int nq = t >> 3, cq = t & 7;
    float acc[8][8] = {};
    for (int ch = 0; ch < 2; ch++) {
        __syncthreads();
        int n = n0 + t;
        if (n < N_NODES) {
            const float4* xr = (const float4*)&x[(size_t)n * F_IN + ch * 64];
#pragma unroll
            for (int j = 0; j < 16; j++) {
                float4 v = xr[j];
                xs[(j * 4 + 0) * 132 + t] = v.x;
                xs[(j * 4 + 1) * 132 + t] = v.y;
                xs[(j * 4 + 2) * 132 + t] = v.z;
                xs[(j * 4 + 3) * 132 + t] = v.w;
            }
        } else {
#pragma unroll
            for (int j = 0; j < 64; j++) xs[j * 132 + t] = 0.f;
        }
        __syncthreads();
#pragma unroll 2
        for (int k = 0; k < 64; k++) {
            float4 a0 = xs4[k * 33 + nq * 2];
            float4 a1 = xs4[k * 33 + nq * 2 + 1];
            int kg = ch * 64 + k;
            float4 w0 = Ws4[kg * 16 + cq * 2];
            float4 w1 = Ws4[kg * 16 + cq * 2 + 1];
            float av[8] = {a0.x, a0.y, a0.z, a0.w, a1.x, a1.y, a1.z, a1.w};
            float wv[8] = {w0.x, w0.y, w0.z, w0.w, w1.x, w1.y, w1.z, w1.w};
#pragma unroll
            for (int i = 0; i < 8; i++)
#pragma unroll
                for (int j = 0; j < 8; j++) acc[i][j] += av[i] * wv[j];
        }
    }
#pragma unroll
    for (int i = 0; i < 8; i++) {
        int n = n0 + nq * 8 + i;
        if (n < N_NODES) {
            *(float4*)&g_xw[n * 64 + cq * 8] =
                make_float4(acc[i][0], acc[i][1], acc[i][2], acc[i][3]);
            *(float4*)&g_xw[n * 64 + cq * 8 + 4] =
                make_float4(acc[i][4], acc[i][5], acc[i][6], acc[i][7]);
        }
    }
}

// ---------------- GCN gather ----------------
__global__ __launch_bounds__(256) void k_gcn_gather() {
    int t = threadIdx.x;
    int n = blockIdx.x * 4 + (t >> 6);
    if (n >= N_NODES) return;
    int c = t & 63;
    int off = g_off[n], dg = g_degi[n];
    float acc = 0.f;
    int rN = (dg > 0) ? g_csr[off] : 0;
    for (int k = 0; k < dg; k++) {
        int r = rN;
        if (k + 1 < dg) rN = g_csr[off + k + 1];
        acc += g_dinv[r] * g_xw[r * 64 + c];
    }
    g_h1[n * 64 + c] = acc * g_dinv[n];
}

// ---------------- dense: hg = relu(gcn) @ Wg (fp16 out) + attention dots ----------------
#define HG_SMEM ((4096 + 1088) * 16)
__global__ __launch_bounds__(256) void k_hg(const float* __restrict__ Wg,
                                            const float* __restrict__ b1,
                                            const float* __restrict__ att_src,
                                            const float* __restrict__ att_dst) {
    extern __shared__ float4 sm4[];
    float4* Ws4 = sm4;           // 64 k x 64 f4
    float4* hs4 = sm4 + 4096;    // 64 k x 17 f4
    float* hs = (float*)hs4;
    int t = threadIdx.x;
    int n0 = blockIdx.x * 64;

#pragma unroll
    for (int i = 0; i < 16; i++) Ws4[t + 256 * i] = ((const float4*)Wg)[t + 256 * i];

    {
        int nl = t & 63, kq = t >> 6;
        int n = n0 + nl;
        if (n < N_NODES) {
            float d = g_dinv[n]; float d2 = d * d;
#pragma unroll
            for (int j = 0; j < 4; j++) {
                int k0 = kq * 16 + j * 4;
                float4 hv = *(const float4*)&g_h1[n * 64 + k0];
                float4 xv = *(const float4*)&g_xw[n * 64 + k0];
                float4 bv = *(const float4*)&b1[k0];
                hs[(k0 + 0) * 68 + nl] = fmaxf(hv.x + d2 * xv.x + bv.x, 0.f);
                hs[(k0 + 1) * 68 + nl] = fmaxf(hv.y + d2 * xv.y + bv.y, 0.f);
                hs[(k0 + 2) * 68 + nl] = fmaxf(hv.z + d2 * xv.z + bv.z, 0.f);
                hs[(k0 + 3) * 68 + nl] = fmaxf(hv.w + d2 * xv.w + bv.w, 0.f);
            }
        } else {
#pragma unroll
            for (int j = 0; j < 16; j++) hs[(kq * 16 + j) * 68 + nl] = 0.f;
        }
    }
    __syncthreads();

    int nq = t >> 5, cq = t & 31;
    int lane = t & 31;
    float acc[8][8] = {};
#pragma unroll 2
    for (int k = 0; k < 64; k++) {
        float4 a0 = hs4[k * 17 + nq * 2];
        float4 a1 = hs4[k * 17 + nq * 2 + 1];
        float4 w0 = Ws4[k * 64 + cq * 2];
        float4 w1 = Ws4[k * 64 + cq * 2 + 1];
        float av[8] = {a0.x, a0.y, a0.z, a0.w, a1.x, a1.y, a1.z, a1.w};
        float wv[8] = {w0.x, w0.y, w0.z, w0.w, w1.x, w1.y, w1.z, w1.w};
#pragma unroll
        for (int i = 0; i < 8; i++)
#pragma unroll
            for (int j = 0; j < 8; j++) acc[i][j] += av[i] * wv[j];
    }
    int c0 = cq * 8;
    float4 s0 = *(const float4*)&att_src[c0];
    float4 s1 = *(const float4*)&att_src[c0 + 4];
    float4 d0 = *(const float4*)&att_dst[c0];
    float4 d1 = *(const float4*)&att_dst[c0 + 4];
    int head = cq >> 3;
#pragma unroll
    for (int i = 0; i < 8; i++) {
        int n = n0 + nq * 8 + i;
        bool valid = (n < N_NODES);
        if (valid) {
            // pack 8 cols to fp16, one 16B store
            __half2 p0 = __floats2half2_rn(acc[i][0], acc[i][1]);
            __half2 p1 = __floats2half2_rn(acc[i][2], acc[i][3]);
            __half2 p2 = __floats2half2_rn(acc[i][4], acc[i][5]);
            __half2 p3 = __floats2half2_rn(acc[i][6], acc[i][7]);
            uint4 pk;
            pk.x = h2_bits(p0); pk.y = h2_bits(p1);
            pk.z = h2_bits(p2); pk.w = h2_bits(p3);
            *(uint4*)&g_hg[(size_t)n * 256 + c0] = pk;
        }
        float sp = acc[i][0] * s0.x + acc[i][1] * s0.y + acc[i][2] * s0.z + acc[i][3] * s0.w
                 + acc[i][4] * s1.x + acc[i][5] * s1.y + acc[i][6] * s1.z + acc[i][7] * s1.w;
        float dp = acc[i][0] * d0.x + acc[i][1] * d0.y + acc[i][2] * d0.z + acc[i][3] * d0.w
                 + acc[i][4] * d1.x + acc[i][5] * d1.y + acc[i][6] * d1.z + acc[i][7] * d1.w;
        sp += __shfl_down_sync(0xffffffffu, sp, 4, 8);
        sp += __shfl_down_sync(0xffffffffu, sp, 2, 8);
        sp += __shfl_down_sync(0xffffffffu, sp, 1, 8);
        dp += __shfl_down_sync(0xffffffffu, dp, 4, 8);
        dp += __shfl_down_sync(0xffffffffu, dp, 2, 8);
        dp += __shfl_down_sync(0xffffffffu, dp, 1, 8);
        if ((lane & 7) == 0 && valid) {
            int o = n * 4 + head;
            g_asrc[o] = sp;
            g_adst[o] = dp;
            g_eself[o] = leaky(sp + dp);
        }
    }
}

// ---------------- GAT softmax: one warp per node, SINGLE pass (fixed shift) ----------------
__global__ __launch_bounds__(256) void k_gat_softmax() {
    int t = threadIdx.x;
    int lane = t & 31;
    int n = blockIdx.x * 8 + (t >> 5);
    if (n >= N_NODES) return;
    int off = g_off[n], dg = g_degi[n];
    float4 dstv = *(const float4*)&g_adst[n * 4];
    float4 es = *(const float4*)&g_eself[n * 4];
    float4 sum = make_float4(0.f, 0.f, 0.f, 0.f);
    for (int p = off + lane; p < off + dg; p += 32) {
        int r = g_csr[p];
        float4 s = *(const float4*)&g_asrc[r * 4];
        float4 ex;
        ex.x = __expf(leaky(s.x + dstv.x) - 20.f);
        ex.y = __expf(leaky(s.y + dstv.y) - 20.f);
        ex.z = __expf(leaky(s.z + dstv.z) - 20.f);
        ex.w = __expf(leaky(s.w + dstv.w) - 20.f);
        *(float4*)&g_alpha[(size_t)p * 4] = ex;
        sum.x += ex.x; sum.y += ex.y; sum.z += ex.z; sum.w += ex.w;
    }
#pragma unroll
    for (int o = 16; o > 0; o >>= 1) {
        sum.x += __shfl_xor_sync(0xffffffffu, sum.x, o);
        sum.y += __shfl_xor_sync(0xffffffffu, sum.y, o);
        sum.z += __shfl_xor_sync(0xffffffffu, sum.z, o);
        sum.w += __shfl_xor_sync(0xffffffffu, sum.w, o);
    }
    if (lane == 0) {
        float4 sf;
        sf.x = __expf(es.x - 20.f); sf.y = __expf(es.y - 20.f);
        sf.z = __expf(es.z - 20.f); sf.w = __expf(es.w - 20.f);
        sum.x += sf.x; sum.y += sf.y; sum.z += sf.z; sum.w += sf.w;
        float4 rs;
        rs.x = 0.25f * __frcp_rn(sum.x); rs.y = 0.25f * __frcp_rn(sum.y);
        rs.z = 0.25f * __frcp_rn(sum.z); rs.w = 0.25f * __frcp_rn(sum.w);
        *(float4*)&g_esum[n * 4] = rs;
        *(float4*)&g_exself[n * 4] = sf;
    }
}

// ---------------- GAT gather (fp16 hg) ----------------
__global__ __launch_bounds__(256) void k_gat_gather() {
    int t = threadIdx.x;
    int n = blockIdx.x * 4 + (t >> 6);
    if (n >= N_NODES) return;
    int c = t & 63;
    int off = g_off[n], dg = g_degi[n];
    float4 rs = *(const float4*)&g_esum[n * 4];
    float4 sf = *(const float4*)&g_exself[n * 4];
    const __half* hgn = &g_hg[(size_t)n * 256 + c];
    float a0 = sf.x * __half2float(hgn[0]);
    float a1 = sf.y * __half2float(hgn[64]);
    float a2 = sf.z * __half2float(hgn[128]);
    float a3 = sf.w * __half2float(hgn[192]);
    int rN = (dg > 0) ? g_csr[off] : 0;
    for (int k = 0; k < dg; k++) {
        int r = rN;
        if (k + 1 < dg) rN = g_csr[off + k + 1];
        float4 ex = *(const float4*)&g_alpha[(size_t)(off + k) * 4];
        const __half* hgr = &g_hg[(size_t)r * 256 + c];
        a0 += ex.x * __half2float(hgr[0]);
        a1 += ex.y * __half2float(hgr[64]);
        a2 += ex.z * __half2float(hgr[128]);
        a3 += ex.w * __half2float(hgr[192]);
    }
    float v = rs.x * a0 + rs.y * a1 + rs.z * a2 + rs.w * a3;
    g_h2[n * 64 + c] = __float2half_rn(v);
}

// ---------------- SAGE gather (fp16 h2) ----------------
__global__ __launch_bounds__(256) void k_sage_gather(const float* __restrict__ bg) {
    int t = threadIdx.x;
    int n = blockIdx.x * 4 + (t >> 6);
    if (n >= N_NODES) return;
    int c = t & 63;
    int off = g_off[n], dg = g_degi[n];
    float bc = bg[c];
    float acc = 0.f;
    int rN = (dg > 0) ? g_csr[off] : 0;
    for (int k = 0; k < dg; k++) {
        int r = rN;
        if (k + 1 < dg) rN = g_csr[off + k + 1];
        acc += fmaxf(__half2float(g_h2[r * 64 + c]) + bc, 0.f);
    }
    g_sagg[n * 64 + c] = acc;
}

// ---------------- final: stacked GEMM [m;h]@[Wl;Wr] + bl, then heads ----------------
#define FIN_SMEM (5184 * 16 + 512)
__global__ __launch_bounds__(128) void k_final(
    const float* __restrict__ bl, const float* __restrict__ Wl,
    const float* __restrict__ Wr, const float* __restrict__ bg,
    const float* __restrict__ a1_w, const float* __restrict__ a1_b,
    const float* __restrict__ a2_w, const float* __restrict__ a2_b,
    const float* __restrict__ r1_w, const float* __restrict__ r1_b,
    const float* __restrict__ r2_w, const float* __restrict__ r2_b,
    float* __restrict__ out) {
    extern __shared__ float4 sm4[];
    float4* Ws4  = sm4;
    float4* xs4  = sm4 + 2048;
    float4* hw14 = sm4 + 4160;
    float* tail = (float*)(sm4 + 5184);
    float* hw2 = tail;
    float* hb1 = tail + 64;
    float* xs  = (float*)xs4;
    float* hw1 = (float*)hw14;
    int t = threadIdx.x;
    int n0 = blockIdx.x * 128;

#pragma unroll
    for (int i = 0; i < 8; i++) {
        Ws4[t + 128 * i]        = ((const float4*)Wl)[t + 128 * i];
        Ws4[1024 + t + 128 * i] = ((const float4*)Wr)[t + 128 * i];
    }
#pragma unroll
    for (int i = 0; i < 4; i++) {
        hw14[t + 128 * i]       = ((const float4*)a1_w)[t + 128 * i];
        hw14[512 + t + 128 * i] = ((const float4*)r1_w)[t + 128 * i];
    }
    if (t < 32) {
        hw2[t] = a2_w[t]; hw2[32 + t] = r2_w[t];
        hb1[t] = a1_b[t]; hb1[32 + t] = r1_b[t];
    }

    int nq = t >> 3, cq = t & 7;
    float4 bl0 = *(const float4*)&bl[cq * 8];
    float4 bl1 = *(const float4*)&bl[cq * 8 + 4];
    float blv[8] = {bl0.x, bl0.y, bl0.z, bl0.w, bl1.x, bl1.y, bl1.z, bl1.w};
    float acc[8][8];
#pragma unroll
    for (int i = 0; i < 8; i++)
#pragma unroll
        for (int j = 0; j < 8; j++) acc[i][j] = blv[j];

    for (int ch = 0; ch < 2; ch++) {
        __syncthreads();
        int n = n0 + t;
        if (n < N_NODES) {
            if (ch == 0) {
                float inv = __frcp_rn(fmaxf((float)g_degi[n], 1.f));
#pragma unroll
                for (int j = 0; j < 16; j++) {
                    float4 v = *(const float4*)&g_sagg[n * 64 + j * 4];
                    xs[(j * 4 + 0) * 132 + t] = v.x * inv;
                    xs[(j * 4 + 1) * 132 + t] = v.y * inv;
                    xs[(j * 4 + 2) * 132 + t] = v.z * inv;
                    xs[(j * 4 + 3) * 132 + t] = v.w * inv;
                }
            } else {
                const uint4* h2r = (const uint4*)&g_h2[n * 64];
#pragma unroll
                for (int j = 0; j < 8; j++) {
                    uint4 pk = h2r[j];
                    float2 f0 = __half22float2(bits_h2(pk.x));
                    float2 f1 = __half22float2(bits_h2(pk.y));
                    float2 f2 = __half22float2(bits_h2(pk.z));
                    float2 f3 = __half22float2(bits_h2(pk.w));
                    int k0 = j * 8;
                    float4 b0 = *(const float4*)&bg[k0];
                    float4 b1v = *(const float4*)&bg[k0 + 4];
                    xs[(k0 + 0) * 132 + t] = fmaxf(f0.x + b0.x, 0.f);
                    xs[(k0 + 1) * 132 + t] = fmaxf(f0.y + b0.y, 0.f);
                    xs[(k0 + 2) * 132 + t] = fmaxf(f1.x + b0.z, 0.f);
                    xs[(k0 + 3) * 132 + t] = fmaxf(f1.y + b0.w, 0.f);
                    xs[(k0 + 4) * 132 + t] = fmaxf(f2.x + b1v.x, 0.f);
                    xs[(k0 + 5) * 132 + t] = fmaxf(f2.y + b1v.y, 0.f);
                    xs[(k0 + 6) * 132 + t] = fmaxf(f3.x + b1v.z, 0.f);
                    xs[(k0 + 7) * 132 + t] = fmaxf(f3.y + b1v.w, 0.f);
                }
            }
        } else {
#pragma unroll
            for (int j = 0; j < 64; j++) xs[j * 132 + t] = 0.f;
        }
        __syncthreads();
#pragma unroll 2
        for (int k = 0; k < 64; k++) {
            float4 a0 = xs4[k * 33 + nq * 2];
            float4 a1 = xs4[k * 33 + nq * 2 + 1];
            int kg = ch * 64 + k;
            float4 w0 = Ws4[kg * 16 + cq * 2];
            float4 w1 = Ws4[kg * 16 + cq * 2 + 1];
            float av[8] = {a0.x, a0.y, a0.z, a0.w, a1.x, a1.y, a1.z, a1.w};
            float wv[8] = {w0.x, w0.y, w0.z, w0.w, w1.x, w1.y, w1.z, w1.w};
#pragma unroll
            for (int i = 0; i < 8; i++)
#pragma unroll
                for (int j = 0; j < 8; j++) acc[i][j] += av[i] * wv[j];
        }
    }
#pragma unroll
    for (int i = 0; i < 8; i++) {
        int n = n0 + nq * 8 + i;
        if (n < N_NODES) {
            *(float4*)&out[(size_t)n * 64 + cq * 8] =
                make_float4(acc[i][0], acc[i][1], acc[i][2], acc[i][3]);
            *(float4*)&out[(size_t)n * 64 + cq * 8 + 4] =
                make_float4(acc[i][4], acc[i][5], acc[i][6], acc[i][7]);
        }
    }
    __syncthreads();

    int w = t >> 5, lane = t & 31;
    int hd = w >> 1, half = w & 1;
    float w1r[64];
#pragma unroll
    for (int c = 0; c < 64; c++) w1r[c] = hw1[hd * 2048 + c * 32 + lane];
    float w2v = hw2[hd * 32 + lane];
    float b1v = hb1[hd * 32 + lane];
    float b2 = hd ? r2_b[0] : a2_b[0];
    for (int ln = half * 64; ln < half * 64 + 64; ln++) {
        int n = n0 + ln;
        if (n >= N_NODES) break;
        float2 ep = *(const float2*)&out[(size_t)n * 64 + lane * 2];
        float z = b1v;
#pragma unroll
        for (int c = 0; c < 64; c++) {
            float ec = __shfl_sync(0xffffffffu, (c & 1) ? ep.y : ep.x, c >> 1);
            z += ec * w1r[c];
        }
        z = fmaxf(z, 0.f) * w2v;
#pragma unroll
        for (int off = 16; off > 0; off >>= 1)
            z += __shfl_down_sync(0xffffffffu, z, off);
        if (lane == 0)
            out[NH + hd * N_NODES + n] = 1.f / (1.f + expf(-(z + b2)));
    }
}

// ---------------- launch ----------------
extern "C" void kernel_launch(void* const* d_in, const int* in_sizes, int n_in,
                              void* d_out, int out_size) {
    const float* x       = (const float*)d_in[0];
    const int*   ei      = (const int*)d_in[1];
    const float* W1      = (const float*)d_in[2];
    const float* b1      = (const float*)d_in[3];
    const float* Wg      = (const float*)d_in[4];
    const float* att_src = (const float*)d_in[5];
    const float* att_dst = (const float*)d_in[6];
    const float* bg      = (const float*)d_in[7];
    const float* Wl      = (const float*)d_in[8];
    const float* bl      = (const float*)d_in[9];
    const float* Wr      = (const float*)d_in[10];
    const float* a1_w    = (const float*)d_in[11];
    const float* a1_b    = (const float*)d_in[12];
    const float* a2_w    = (const float*)d_in[13];
    const float* a2_b    = (const float*)d_in[14];
    const float* r1_w    = (const float*)d_in[15];
    const float* r1_b    = (const float*)d_in[16];
    const float* r2_w    = (const float*)d_in[17];
    const float* r2_b    = (const float*)d_in[18];
    float* out = (float*)d_out;

    int E = in_sizes[1] / 2;
    const int T = 256;
    int gE = (E + T - 1) / T;
    int gN = (N_NODES + T - 1) / T;
    int gN4 = (N_NODES + 3) / 4;
    int gN8 = (N_NODES + 7) / 8;

    cudaFuncSetAttribute(k_xw,    cudaFuncAttributeMaxDynamicSharedMemorySize, XW_SMEM);
    cudaFuncSetAttribute(k_hg,    cudaFuncAttributeMaxDynamicSharedMemorySize, HG_SMEM);
    cudaFuncSetAttribute(k_final, cudaFuncAttributeMaxDynamicSharedMemorySize, FIN_SMEM);

    k_zero_deg<<<gN, T>>>();
    k_degcnt<<<gE, T>>>(ei, E);
    k_scan1<<<NB, 256>>>();
    k_scan2<<<1, 256>>>();
    k_scan3<<<gN, T>>>();
    k_fill<<<gE, T>>>(ei, E);
    k_xw<<<(N_NODES + 127) / 128, 128, XW_SMEM>>>(x, W1);
    k_gcn_gather<<<gN4, 256>>>();
    k_hg<<<(N_NODES + 63) / 64, 256, HG_SMEM>>>(Wg, b1, att_src, att_dst);
    k_gat_softmax<<<gN8, 256>>>();
    k_gat_gather<<<gN4, 256>>>();
    k_sage_gather<<<gN4, 256>>>(bg);
    k_final<<<(N_NODES + 127) / 128, 128, FIN_SMEM>>>(bl, Wl, Wr, bg,
                                                      a1_w, a1_b, a2_w, a2_b,
                                                      r1_w, r1_b, r2_w, r2_b, out);
}